// round 1
// baseline (speedup 1.0000x reference)
#include <cuda_runtime.h>
#include <math.h>

#define NE 8
#define NK 2
#define DM 1024
#define NB 4
#define NS 2048
#define NT (NB * NS)        // 8192 tokens
#define NP (NT * NK)        // 16384 (token,slot) pairs

// ---------------- scratch (device globals; no allocation allowed) ----------
__device__ float g_h[(size_t)NP * DM];   // 64 MB hidden activations
__device__ int   g_order[NP];            // compacted pair indices per expert
__device__ float g_w[NP];                // combine weight per (token,slot)
__device__ int   g_eid[NP];              // expert id per (token,slot)
__device__ int   g_count[NE];
__device__ int   g_off[NE];
__device__ int   g_pos[NE];
__device__ float g_zsum;
__device__ float g_proxy[NB * NE];
__device__ float g_dens[NB * NE];

// ---------------- kernel 1: zero output + counters -------------------------
__global__ void zero_kernel(float* __restrict__ out, int n) {
    int i = blockIdx.x * blockDim.x + threadIdx.x;
    int stride = gridDim.x * blockDim.x;
    for (; i < n; i += stride) out[i] = 0.0f;
    if (blockIdx.x == 0) {
        int t = threadIdx.x;
        if (t < NE) { g_count[t] = 0; g_pos[t] = 0; }
        if (t == 0) g_zsum = 0.0f;
        if (t < NB * NE) { g_proxy[t] = 0.0f; g_dens[t] = 0.0f; }
    }
}

// ---------------- kernel 2: gating ----------------------------------------
// one block per token; 8 warps compute the 8 expert dot products
__global__ __launch_bounds__(256) void gate_kernel(
    const float* __restrict__ x, const float* __restrict__ Wg) {
    __shared__ float xs[DM];
    __shared__ float logits[NE];
    int t = blockIdx.x;
    const float* xr = x + (size_t)t * DM;
    for (int i = threadIdx.x; i < DM; i += blockDim.x) xs[i] = xr[i];
    __syncthreads();
    int w = threadIdx.x >> 5, lane = threadIdx.x & 31;
    const float* wg = Wg + w * DM;
    float s = 0.0f;
    for (int k = lane; k < DM; k += 32) s += xs[k] * wg[k];
#pragma unroll
    for (int o = 16; o; o >>= 1) s += __shfl_xor_sync(0xffffffffu, s, o);
    if (lane == 0) logits[w] = s;
    __syncthreads();
    if (threadIdx.x == 0) {
        float m = -1e30f;
#pragma unroll
        for (int e = 0; e < NE; e++) m = fmaxf(m, logits[e]);
        float p[NE], sum = 0.0f;
#pragma unroll
        for (int e = 0; e < NE; e++) { p[e] = expf(logits[e] - m); sum += p[e]; }
        float inv_sum = 1.0f / sum;
        float z = m + logf(sum);
        atomicAdd(&g_zsum, z * z);
        int b = t / NS;
#pragma unroll
        for (int e = 0; e < NE; e++) atomicAdd(&g_proxy[b * NE + e], p[e] * inv_sum);
        // top-2 (first-index wins on ties, matching jax top_k)
        int i0 = 0;
#pragma unroll
        for (int e = 1; e < NE; e++) if (p[e] > p[i0]) i0 = e;
        int i1 = (i0 == 0) ? 1 : 0;
#pragma unroll
        for (int e = 0; e < NE; e++) if (e != i0 && p[e] > p[i1]) i1 = e;
        atomicAdd(&g_dens[b * NE + i0], 1.0f);
        float v0 = p[i0], v1 = p[i1];
        float invw = 1.0f / (v0 + v1);
        g_w[2 * t]     = v0 * invw;
        g_w[2 * t + 1] = v1 * invw;
        g_eid[2 * t]     = i0;
        g_eid[2 * t + 1] = i1;
        atomicAdd(&g_count[i0], 1);
        atomicAdd(&g_count[i1], 1);
    }
}

// ---------------- kernel 3: exclusive scan (E=8, trivial) ------------------
__global__ void scan_kernel() {
    if (threadIdx.x == 0 && blockIdx.x == 0) {
        int acc = 0;
#pragma unroll
        for (int e = 0; e < NE; e++) { g_off[e] = acc; acc += g_count[e]; }
    }
}

// ---------------- kernel 4: scatter pairs into expert buckets --------------
__global__ void scatter_kernel() {
    int p = blockIdx.x * blockDim.x + threadIdx.x;
    if (p >= NP) return;
    int e = g_eid[p];
    int idx = atomicAdd(&g_pos[e], 1);
    g_order[g_off[e] + idx] = p;   // p>>1 = token, p&1 = slot
}

// ---------------- GEMM helpers ---------------------------------------------
__device__ __forceinline__ float gelu_exact(float v) {
    return 0.5f * v * (1.0f + erff(v * 0.70710678118654752f));
}

// tile: 64 rows x 64 cols, 256 threads, 4x4 per thread, k-chunk 16
// gemm1: h[p_row] = gelu( x[token] @ W1[e] + b1[e] )
__global__ __launch_bounds__(256) void gemm1_kernel(
    const float* __restrict__ x, const float* __restrict__ W1,
    const float* __restrict__ b1) {
    int e = blockIdx.z;
    int cnt = g_count[e];
    int row0 = blockIdx.x * 64;
    if (row0 >= cnt) return;
    int col0 = blockIdx.y * 64;
    int base = g_off[e];

    __shared__ float As[16][68];
    __shared__ float Bs[16][64];
    __shared__ int toks[64];

    int tid = threadIdx.x;
    if (tid < 64) {
        int r = row0 + tid;
        toks[tid] = (r < cnt) ? (g_order[base + r] >> 1) : -1;
    }
    __syncthreads();

    const float* Wb = W1 + (size_t)e * DM * DM;
    float acc[4][4];
#pragma unroll
    for (int i = 0; i < 4; i++)
#pragma unroll
        for (int j = 0; j < 4; j++) acc[i][j] = 0.0f;

    int ty = tid >> 4, tx = tid & 15;
    int ar = tid >> 2, akq = tid & 3;      // A loader: row, k-quad
    int bkk = tid >> 4, bnq = tid & 15;    // B loader: k, n-quad

    for (int k0 = 0; k0 < DM; k0 += 16) {
        float4 av = make_float4(0.f, 0.f, 0.f, 0.f);
        int tk = toks[ar];
        if (tk >= 0)
            av = *(const float4*)(x + (size_t)tk * DM + k0 + akq * 4);
        As[akq * 4 + 0][ar] = av.x;
        As[akq * 4 + 1][ar] = av.y;
        As[akq * 4 + 2][ar] = av.z;
        As[akq * 4 + 3][ar] = av.w;
        float4 bv = *(const float4*)(Wb + (size_t)(k0 + bkk) * DM + col0 + bnq * 4);
        *(float4*)&Bs[bkk][bnq * 4] = bv;
        __syncthreads();
#pragma unroll
        for (int kk = 0; kk < 16; kk++) {
            float4 a4 = *(float4*)&As[kk][ty * 4];
            float4 b4 = *(float4*)&Bs[kk][tx * 4];
            float a[4] = {a4.x, a4.y, a4.z, a4.w};
            float b[4] = {b4.x, b4.y, b4.z, b4.w};
#pragma unroll
            for (int i = 0; i < 4; i++)
#pragma unroll
                for (int j = 0; j < 4; j++) acc[i][j] += a[i] * b[j];
        }
        __syncthreads();
    }

#pragma unroll
    for (int i = 0; i < 4; i++) {
        int r = row0 + ty * 4 + i;
        if (r >= cnt) continue;
        size_t hrow = (size_t)(base + r) * DM;
#pragma unroll
        for (int j = 0; j < 4; j++) {
            int c = col0 + tx * 4 + j;
            float v = acc[i][j] + b1[e * DM + c];
            g_h[hrow + c] = gelu_exact(v);
        }
    }
}

// gemm2: out[token] += w * ( h[p_row] @ W2[e] + b2[e] )
__global__ __launch_bounds__(256) void gemm2_kernel(
    const float* __restrict__ W2, const float* __restrict__ b2,
    float* __restrict__ out) {
    int e = blockIdx.z;
    int cnt = g_count[e];
    int row0 = blockIdx.x * 64;
    if (row0 >= cnt) return;
    int col0 = blockIdx.y * 64;
    int base = g_off[e];

    __shared__ float As[16][68];
    __shared__ float Bs[16][64];

    int tid = threadIdx.x;
    const float* Wb = W2 + (size_t)e * DM * DM;
    float acc[4][4];
#pragma unroll
    for (int i = 0; i < 4; i++)
#pragma unroll
        for (int j = 0; j < 4; j++) acc[i][j] = 0.0f;

    int ty = tid >> 4, tx = tid & 15;
    int ar = tid >> 2, akq = tid & 3;
    int bkk = tid >> 4, bnq = tid & 15;

    for (int k0 = 0; k0 < DM; k0 += 16) {
        float4 av = make_float4(0.f, 0.f, 0.f, 0.f);
        int r = row0 + ar;
        if (r < cnt)
            av = *(const float4*)(g_h + (size_t)(base + r) * DM + k0 + akq * 4);
        As[akq * 4 + 0][ar] = av.x;
        As[akq * 4 + 1][ar] = av.y;
        As[akq * 4 + 2][ar] = av.z;
        As[akq * 4 + 3][ar] = av.w;
        float4 bv = *(const float4*)(Wb + (size_t)(k0 + bkk) * DM + col0 + bnq * 4);
        *(float4*)&Bs[bkk][bnq * 4] = bv;
        __syncthreads();
#pragma unroll
        for (int kk = 0; kk < 16; kk++) {
            float4 a4 = *(float4*)&As[kk][ty * 4];
            float4 b4 = *(float4*)&Bs[kk][tx * 4];
            float a[4] = {a4.x, a4.y, a4.z, a4.w};
            float b[4] = {b4.x, b4.y, b4.z, b4.w};
#pragma unroll
            for (int i = 0; i < 4; i++)
#pragma unroll
                for (int j = 0; j < 4; j++) acc[i][j] += a[i] * b[j];
        }
        __syncthreads();
    }

#pragma unroll
    for (int i = 0; i < 4; i++) {
        int r = row0 + ty * 4 + i;
        if (r >= cnt) continue;
        int p = g_order[base + r];
        int t = p >> 1;
        float w = g_w[p];
#pragma unroll
        for (int j = 0; j < 4; j++) {
            int c = col0 + tx * 4 + j;
            float v = (acc[i][j] + b2[e * DM + c]) * w;
            atomicAdd(&out[(size_t)t * DM + c], v);
        }
    }
}

// ---------------- kernel 7: losses -----------------------------------------
__global__ void finalize_kernel(float* __restrict__ out) {
    if (blockIdx.x == 0 && threadIdx.x == 0) {
        float zloss = g_zsum / (float)NT;
        float bal = 0.0f;
#pragma unroll
        for (int i = 0; i < NB * NE; i++)
            bal += (g_proxy[i] / (float)NS) * (g_dens[i] / (float)NS);
        bal = bal / (float)(NB * NE) * (float)(NE * NE);
        out[(size_t)NT * DM]     = bal * 0.01f + zloss * 0.001f;
        out[(size_t)NT * DM + 1] = bal;
    }
}

// ---------------- launch ----------------------------------------------------
extern "C" void kernel_launch(void* const* d_in, const int* in_sizes, int n_in,
                              void* d_out, int out_size) {
    const float* x  = (const float*)d_in[0];
    const float* Wg = (const float*)d_in[1];
    const float* W1 = (const float*)d_in[2];
    const float* b1 = (const float*)d_in[3];
    const float* W2 = (const float*)d_in[4];
    const float* b2 = (const float*)d_in[5];
    float* out = (float*)d_out;

    zero_kernel<<<4096, 256>>>(out, NT * DM);
    gate_kernel<<<NT, 256>>>(x, Wg);
    scan_kernel<<<1, 32>>>();
    scatter_kernel<<<NP / 256, 256>>>();
    dim3 ggrid(128, 16, NE);   // 128 row-tiles covers worst case 8192 rows/expert
    gemm1_kernel<<<ggrid, 256>>>(x, W1, b1);
    gemm2_kernel<<<ggrid, 256>>>(W2, b2, out);
    finalize_kernel<<<1, 32>>>(out);
}

// round 4
// speedup vs baseline: 2.2918x; 2.2918x over previous
#include <cuda_runtime.h>
#include <cuda_bf16.h>
#include <math.h>
#include <stdint.h>

#define NE 8
#define DM 1024
#define NBz 4
#define NSz 2048
#define NT 8192           // tokens
#define NP 16384          // (token,slot) pairs

// ---------------- device scratch (no allocation allowed) -------------------
__device__ __align__(1024) __nv_bfloat16 g_xhi[(size_t)NT * DM];
__device__ __align__(1024) __nv_bfloat16 g_xlo[(size_t)NT * DM];
__device__ __align__(1024) __nv_bfloat16 g_w1hi[(size_t)NE * DM * DM];
__device__ __align__(1024) __nv_bfloat16 g_w1lo[(size_t)NE * DM * DM];
__device__ __align__(1024) __nv_bfloat16 g_w2hi[(size_t)NE * DM * DM];
__device__ __align__(1024) __nv_bfloat16 g_w2lo[(size_t)NE * DM * DM];
__device__ __align__(1024) __nv_bfloat16 g_hhi[(size_t)NP * DM];
__device__ __align__(1024) __nv_bfloat16 g_hlo[(size_t)NP * DM];
__device__ __align__(1024) float g_y[(size_t)NP * DM];
__device__ int   g_order[NP];
__device__ float g_wt[NP];
__device__ int   g_eid[NP];
__device__ int   g_count[NE], g_off[NE], g_pos[NE];
__device__ float g_zsum, g_proxy[NBz * NE], g_dens[NBz * NE];

// ---------------- helpers ---------------------------------------------------
__device__ __forceinline__ uint32_t smem_u32(const void* p) {
    uint32_t a;
    asm("{ .reg .u64 t; cvta.to.shared.u64 t, %1; cvt.u32.u64 %0, t; }" : "=r"(a) : "l"(p));
    return a;
}
__device__ __forceinline__ void cp16(uint32_t dst, const void* src) {
    asm volatile("cp.async.cg.shared.global [%0], [%1], 16;" :: "r"(dst), "l"(src));
}
__device__ __forceinline__ void cp_commit() { asm volatile("cp.async.commit_group;" ::: "memory"); }
__device__ __forceinline__ void cp_wait1() { asm volatile("cp.async.wait_group 1;" ::: "memory"); }
__device__ __forceinline__ void cp_wait0() { asm volatile("cp.async.wait_group 0;" ::: "memory"); }

__device__ __forceinline__ void ldmat4(uint32_t* r, uint32_t addr) {
    asm volatile("ldmatrix.sync.aligned.m8n8.x4.shared.b16 {%0,%1,%2,%3}, [%4];"
                 : "=r"(r[0]), "=r"(r[1]), "=r"(r[2]), "=r"(r[3]) : "r"(addr));
}
__device__ __forceinline__ void ldmat2(uint32_t* r, uint32_t addr) {
    asm volatile("ldmatrix.sync.aligned.m8n8.x2.shared.b16 {%0,%1}, [%2];"
                 : "=r"(r[0]), "=r"(r[1]) : "r"(addr));
}
__device__ __forceinline__ void mma_bf16(float* c, const uint32_t* a, const uint32_t* b) {
    asm volatile("mma.sync.aligned.m16n8k16.row.col.f32.bf16.bf16.f32 "
                 "{%0,%1,%2,%3}, {%4,%5,%6,%7}, {%8,%9}, {%0,%1,%2,%3};"
                 : "+f"(c[0]), "+f"(c[1]), "+f"(c[2]), "+f"(c[3])
                 : "r"(a[0]), "r"(a[1]), "r"(a[2]), "r"(a[3]), "r"(b[0]), "r"(b[1]));
}
__device__ __forceinline__ float gelu_exact(float v) {
    return 0.5f * v * (1.0f + erff(v * 0.70710678118654752f));
}

// ---------------- init / gating / scatter ----------------------------------
__global__ void init_kernel() {
    int t = threadIdx.x;
    if (t < NE) { g_count[t] = 0; g_pos[t] = 0; }
    if (t == 0) g_zsum = 0.0f;
    if (t < NBz * NE) { g_proxy[t] = 0.0f; g_dens[t] = 0.0f; }
}

__global__ __launch_bounds__(256) void gate_kernel(
    const float* __restrict__ x, const float* __restrict__ Wg) {
    __shared__ float xs[DM];
    __shared__ float logits[NE];
    int t = blockIdx.x;
    const float* xr = x + (size_t)t * DM;
    for (int i = threadIdx.x; i < DM; i += blockDim.x) xs[i] = xr[i];
    __syncthreads();
    int w = threadIdx.x >> 5, lane = threadIdx.x & 31;
    const float* wg = Wg + w * DM;
    float s = 0.0f;
    for (int k = lane; k < DM; k += 32) s += xs[k] * wg[k];
#pragma unroll
    for (int o = 16; o; o >>= 1) s += __shfl_xor_sync(0xffffffffu, s, o);
    if (lane == 0) logits[w] = s;
    __syncthreads();
    if (threadIdx.x == 0) {
        float m = -1e30f;
#pragma unroll
        for (int e = 0; e < NE; e++) m = fmaxf(m, logits[e]);
        float p[NE], sum = 0.0f;
#pragma unroll
        for (int e = 0; e < NE; e++) { p[e] = expf(logits[e] - m); sum += p[e]; }
        float inv_sum = 1.0f / sum;
        float z = m + logf(sum);
        atomicAdd(&g_zsum, z * z);
        int b = t / NSz;
#pragma unroll
        for (int e = 0; e < NE; e++) atomicAdd(&g_proxy[b * NE + e], p[e] * inv_sum);
        int i0 = 0;
#pragma unroll
        for (int e = 1; e < NE; e++) if (p[e] > p[i0]) i0 = e;
        int i1 = (i0 == 0) ? 1 : 0;
#pragma unroll
        for (int e = 0; e < NE; e++) if (e != i0 && p[e] > p[i1]) i1 = e;
        atomicAdd(&g_dens[b * NE + i0], 1.0f);
        float v0 = p[i0], v1 = p[i1];
        float invw = 1.0f / (v0 + v1);
        g_wt[2 * t] = v0 * invw;
        g_wt[2 * t + 1] = v1 * invw;
        g_eid[2 * t] = i0;
        g_eid[2 * t + 1] = i1;
        atomicAdd(&g_count[i0], 1);
        atomicAdd(&g_count[i1], 1);
    }
}

__global__ void scan_kernel() {
    if (threadIdx.x == 0) {
        int acc = 0;
#pragma unroll
        for (int e = 0; e < NE; e++) { g_off[e] = acc; acc += g_count[e]; }
    }
}

__global__ void scatter_kernel() {
    int p = blockIdx.x * blockDim.x + threadIdx.x;
    if (p >= NP) return;
    int e = g_eid[p];
    int idx = atomicAdd(&g_pos[e], 1);
    g_order[g_off[e] + idx] = p;
}

// ---------------- conversions ----------------------------------------------
__global__ __launch_bounds__(256) void split_x_kernel(const float* __restrict__ x) {
    size_t i = (size_t)blockIdx.x * 256 + threadIdx.x;   // over NT*DM/4 float4s
    float4 v = ((const float4*)x)[i];
    __nv_bfloat16 h0 = __float2bfloat16_rn(v.x), h1 = __float2bfloat16_rn(v.y);
    __nv_bfloat16 h2 = __float2bfloat16_rn(v.z), h3 = __float2bfloat16_rn(v.w);
    __nv_bfloat16 l0 = __float2bfloat16_rn(v.x - __bfloat162float(h0));
    __nv_bfloat16 l1 = __float2bfloat16_rn(v.y - __bfloat162float(h1));
    __nv_bfloat16 l2 = __float2bfloat16_rn(v.z - __bfloat162float(h2));
    __nv_bfloat16 l3 = __float2bfloat16_rn(v.w - __bfloat162float(h3));
    ((__nv_bfloat162*)g_xhi)[2 * i]     = __nv_bfloat162(h0, h1);
    ((__nv_bfloat162*)g_xhi)[2 * i + 1] = __nv_bfloat162(h2, h3);
    ((__nv_bfloat162*)g_xlo)[2 * i]     = __nv_bfloat162(l0, l1);
    ((__nv_bfloat162*)g_xlo)[2 * i + 1] = __nv_bfloat162(l2, l3);
}

// transpose + split:  wt[e][n][k] = W[e][k][n]
__global__ __launch_bounds__(256) void conv_w_kernel(
    const float* __restrict__ W1, const float* __restrict__ W2) {
    __shared__ float tile[32][33];
    int e = blockIdx.z & 7;
    int which = blockIdx.z >> 3;
    const float* W = which ? W2 : W1;
    __nv_bfloat16* whi = which ? g_w2hi : g_w1hi;
    __nv_bfloat16* wlo = which ? g_w2lo : g_w1lo;
    size_t base = (size_t)e * DM * DM;
    int n0 = blockIdx.x * 32, k0 = blockIdx.y * 32;
    int tx = threadIdx.x & 31, ty = threadIdx.x >> 5;  // 32 x 8
#pragma unroll
    for (int j = 0; j < 4; j++)
        tile[ty + 8 * j][tx] = W[base + (size_t)(k0 + ty + 8 * j) * DM + n0 + tx];
    __syncthreads();
#pragma unroll
    for (int j = 0; j < 4; j++) {
        float v = tile[tx][ty + 8 * j];
        __nv_bfloat16 h = __float2bfloat16_rn(v);
        __nv_bfloat16 l = __float2bfloat16_rn(v - __bfloat162float(h));
        size_t o = base + (size_t)(n0 + ty + 8 * j) * DM + k0 + tx;
        whi[o] = h;
        wlo[o] = l;
    }
}

// ---------------- HMMA GEMM (mma.sync bf16, hi/lo split) -------------------
// CTA tile 128x128, K chunk 32, 8 warps (2x4), warp tile 64x32, 3-stage cp.async
#define BM 128
#define BN 128
#define BK 32
#define NCHUNK (DM / BK)                 // 32
#define TSTRIDE 144                      // bytes per smem row (64B data + 80B pad)
#define TILE_BYTES (BM * TSTRIDE)        // 18432
#define ST_OFF(s)  ((s) * 4 * TILE_BYTES)
#define AHI_OFF(s) (ST_OFF(s))
#define ALO_OFF(s) (ST_OFF(s) + TILE_BYTES)
#define BHI_OFF(s) (ST_OFF(s) + 2 * TILE_BYTES)
#define BLO_OFF(s) (ST_OFF(s) + 3 * TILE_BYTES)
#define TOKS_OFF   (3 * 4 * TILE_BYTES)  // 221184
#define PV_OFF     (TOKS_OFF + 512)
#define WV_OFF     (PV_OFF + 512)
#define SMEM_TOTAL (WV_OFF + 512)        // 222720

template <int PHASE>
__global__ __launch_bounds__(256, 1) void moe_gemm(const float* __restrict__ bias) {
    int e = blockIdx.z;
    int cnt = g_count[e];
    int row0 = blockIdx.x * BM;
    if (row0 >= cnt) return;
    int n0 = blockIdx.y * BN;
    int base = g_off[e];

    extern __shared__ char smem[];
    uint32_t sb = smem_u32(smem);
    int tid = threadIdx.x;
    int wid = tid >> 5, lane = tid & 31;
    int wr = wid >> 2, wc = wid & 3;      // 2 x 4 warp grid
    int m0w = wr * 64, n0w = wc * 32;

    int* toks = (int*)(smem + TOKS_OFF);
    if (tid < BM) {
        int r = row0 + tid;
        if (PHASE == 1) {
            toks[tid] = (r < cnt) ? (g_order[base + r] >> 1) : 0;
        } else {
            toks[tid] = (r < cnt) ? (base + r) : 0;
            int p = (r < cnt) ? g_order[base + r] : 0;
            ((int*)(smem + PV_OFF))[tid] = p;
            ((float*)(smem + WV_OFF))[tid] = g_wt[p];
        }
    }
    __syncthreads();

    const __nv_bfloat16* Ahi = (PHASE == 1) ? g_xhi : g_hhi;
    const __nv_bfloat16* Alo = (PHASE == 1) ? g_xlo : g_hlo;
    const __nv_bfloat16* Whi = ((PHASE == 1) ? g_w1hi : g_w2hi) + (size_t)e * DM * DM;
    const __nv_bfloat16* Wlo = ((PHASE == 1) ? g_w1lo : g_w2lo) + (size_t)e * DM * DM;

    float acc[4][4][4];
#pragma unroll
    for (int i = 0; i < 4; i++)
#pragma unroll
        for (int j = 0; j < 4; j++)
#pragma unroll
            for (int q = 0; q < 4; q++) acc[i][j][q] = 0.0f;

    auto load_chunk = [&](int c, int s) {
        int k0 = c * BK;
#pragma unroll
        for (int it = 0; it < 2; it++) {
            int i = tid + it * 256;          // 0..511
            int r = i >> 2, c16 = i & 3;
            uint32_t so = r * TSTRIDE + c16 * 16;
            const __nv_bfloat16* asrc = (size_t)toks[r] * DM + k0 + c16 * 8 + (const __nv_bfloat16*)0 + 0;
            (void)asrc;
            size_t aoff = (size_t)toks[r] * DM + k0 + c16 * 8;
            size_t boff = (size_t)(n0 + r) * DM + k0 + c16 * 8;
            cp16(sb + AHI_OFF(s) + so, Ahi + aoff);
            cp16(sb + ALO_OFF(s) + so, Alo + aoff);
            cp16(sb + BHI_OFF(s) + so, Whi + boff);
            cp16(sb + BLO_OFF(s) + so, Wlo + boff);
        }
        cp_commit();
    };

    auto compute = [&](int s) {
#pragma unroll
        for (int kk = 0; kk < 2; kk++) {
            int kb = kk * 16;
            uint32_t ah[4][4], al[4][4], bh[4][2], bl[4][2];
            int arow = m0w + (lane & 15);
            int acolb = (kb + ((lane & 16) ? 8 : 0)) * 2;
#pragma unroll
            for (int i = 0; i < 4; i++) {
                uint32_t addr = sb + AHI_OFF(s) + (arow + i * 16) * TSTRIDE + acolb;
                ldmat4(ah[i], addr);
                ldmat4(al[i], addr + TILE_BYTES);
            }
            int brow = lane & 7;
            int bcolb = (kb + ((lane & 8) ? 8 : 0)) * 2;
#pragma unroll
            for (int j = 0; j < 4; j++) {
                uint32_t addr = sb + BHI_OFF(s) + (n0w + j * 8 + brow) * TSTRIDE + bcolb;
                ldmat2(bh[j], addr);
                ldmat2(bl[j], addr + TILE_BYTES);
            }
            // three product passes; 16 independent accumulators between reuses
#pragma unroll
            for (int i = 0; i < 4; i++)
#pragma unroll
                for (int j = 0; j < 4; j++) mma_bf16(acc[i][j], ah[i], bh[j]);
#pragma unroll
            for (int i = 0; i < 4; i++)
#pragma unroll
                for (int j = 0; j < 4; j++) mma_bf16(acc[i][j], ah[i], bl[j]);
#pragma unroll
            for (int i = 0; i < 4; i++)
#pragma unroll
                for (int j = 0; j < 4; j++) mma_bf16(acc[i][j], al[i], bh[j]);
        }
    };

    load_chunk(0, 0);
    load_chunk(1, 1);
    for (int c = 0; c < NCHUNK; c++) {
        int s = c % 3;
        if (c < NCHUNK - 1) cp_wait1(); else cp_wait0();
        __syncthreads();
        if (c + 2 < NCHUNK) load_chunk(c + 2, (c + 2) % 3);
        compute(s);
    }

    // ---------------- epilogue ----------------
#pragma unroll
    for (int i = 0; i < 4; i++) {
        int rb = m0w + i * 16 + (lane >> 2);
#pragma unroll
        for (int j = 0; j < 4; j++) {
            int gcol = n0 + n0w + j * 8 + (lane & 3) * 2;
            float bv0 = bias[e * DM + gcol];
            float bv1 = bias[e * DM + gcol + 1];
#pragma unroll
            for (int h = 0; h < 2; h++) {
                int r = rb + h * 8;
                if (row0 + r >= cnt) continue;
                float v0 = acc[i][j][2 * h]     + bv0;
                float v1 = acc[i][j][2 * h + 1] + bv1;
                if (PHASE == 1) {
                    float gg0 = gelu_exact(v0), gg1 = gelu_exact(v1);
                    __nv_bfloat16 h0 = __float2bfloat16_rn(gg0);
                    __nv_bfloat16 h1 = __float2bfloat16_rn(gg1);
                    __nv_bfloat16 l0 = __float2bfloat16_rn(gg0 - __bfloat162float(h0));
                    __nv_bfloat16 l1 = __float2bfloat16_rn(gg1 - __bfloat162float(h1));
                    uint32_t hv = ((uint32_t)*(uint16_t*)&h1 << 16) | *(uint16_t*)&h0;
                    uint32_t lv = ((uint32_t)*(uint16_t*)&l1 << 16) | *(uint16_t*)&l0;
                    size_t o = (size_t)(base + row0 + r) * DM + gcol;
                    *(uint32_t*)(g_hhi + o) = hv;
                    *(uint32_t*)(g_hlo + o) = lv;
                } else {
                    float wv = ((float*)(smem + WV_OFF))[r];
                    int p = ((int*)(smem + PV_OFF))[r];
                    float2 v = make_float2(v0 * wv, v1 * wv);
                    *(float2*)(g_y + (size_t)p * DM + gcol) = v;
                }
            }
        }
    }
}

// ---------------- combine + losses -----------------------------------------
__global__ __launch_bounds__(256) void combine_kernel(float* __restrict__ out) {
    size_t i = (size_t)blockIdx.x * 256 + threadIdx.x;  // over NT*DM/4 float4s
    size_t t = i >> 8, c = i & 255;
    const float4* y4 = (const float4*)g_y;
    float4 a = y4[(2 * t) * (DM / 4) + c];
    float4 b = y4[(2 * t + 1) * (DM / 4) + c];
    float4 o;
    o.x = a.x + b.x; o.y = a.y + b.y; o.z = a.z + b.z; o.w = a.w + b.w;
    ((float4*)out)[t * (DM / 4) + c] = o;
}

__global__ void finalize_kernel(float* __restrict__ out) {
    if (threadIdx.x == 0) {
        float zloss = g_zsum / (float)NT;
        float bal = 0.0f;
#pragma unroll
        for (int i = 0; i < NBz * NE; i++)
            bal += (g_proxy[i] / (float)NSz) * (g_dens[i] / (float)NSz);
        bal = bal / (float)(NBz * NE) * (float)(NE * NE);
        out[(size_t)NT * DM]     = bal * 0.01f + zloss * 0.001f;
        out[(size_t)NT * DM + 1] = bal;
    }
}

// ---------------- launch ----------------------------------------------------
extern "C" void kernel_launch(void* const* d_in, const int* in_sizes, int n_in,
                              void* d_out, int out_size) {
    const float* x  = (const float*)d_in[0];
    const float* Wg = (const float*)d_in[1];
    const float* W1 = (const float*)d_in[2];
    const float* b1 = (const float*)d_in[3];
    const float* W2 = (const float*)d_in[4];
    const float* b2 = (const float*)d_in[5];
    float* out = (float*)d_out;

    cudaFuncSetAttribute(moe_gemm<1>, cudaFuncAttributeMaxDynamicSharedMemorySize, SMEM_TOTAL);
    cudaFuncSetAttribute(moe_gemm<2>, cudaFuncAttributeMaxDynamicSharedMemorySize, SMEM_TOTAL);

    init_kernel<<<1, 32>>>();
    gate_kernel<<<NT, 256>>>(x, Wg);
    scan_kernel<<<1, 32>>>();
    scatter_kernel<<<NP / 256, 256>>>();
    split_x_kernel<<<NT * DM / 4 / 256, 256>>>(x);
    conv_w_kernel<<<dim3(32, 32, 16), 256>>>(W1, W2);

    dim3 ggrid(64, 8, NE);
    moe_gemm<1><<<ggrid, 256, SMEM_TOTAL>>>(b1);
    moe_gemm<2><<<ggrid, 256, SMEM_TOTAL>>>(b2);
    combine_kernel<<<NT * DM / 4 / 256, 256>>>(out);
    finalize_kernel<<<1, 32>>>(out);
}

// round 6
// speedup vs baseline: 2.9094x; 1.2695x over previous
#include <cuda_runtime.h>
#include <cuda_fp16.h>
#include <cuda_bf16.h>
#include <math.h>
#include <stdint.h>

#define NE 8
#define DM 1024
#define NBz 4
#define NSz 2048
#define NT 8192           // tokens
#define NP 16384          // (token,slot) pairs

// ---------------- device scratch (no allocation allowed) -------------------
__device__ __align__(1024) __half g_xhi[(size_t)NT * DM];
__device__ __align__(1024) __half g_xlo[(size_t)NT * DM];
__device__ __align__(1024) __half g_w1h[(size_t)NE * DM * DM];
__device__ __align__(1024) __half g_w2h[(size_t)NE * DM * DM];
__device__ __align__(1024) __half g_hhi[(size_t)NP * DM];
__device__ __align__(1024) __half g_hlo[(size_t)NP * DM];
__device__ __align__(1024) float g_y[(size_t)NP * DM];
__device__ int   g_order[NP];
__device__ float g_wt[NP];
__device__ int   g_eid[NP];
__device__ int   g_count[NE], g_off[NE], g_pos[NE];
__device__ float g_zsum, g_proxy[NBz * NE], g_dens[NBz * NE];

// ---------------- helpers ---------------------------------------------------
__device__ __forceinline__ uint32_t smem_u32(const void* p) {
    uint32_t a;
    asm("{ .reg .u64 t; cvta.to.shared.u64 t, %1; cvt.u32.u64 %0, t; }" : "=r"(a) : "l"(p));
    return a;
}
__device__ __forceinline__ void cp16(uint32_t dst, const void* src) {
    asm volatile("cp.async.cg.shared.global [%0], [%1], 16;" :: "r"(dst), "l"(src));
}
__device__ __forceinline__ void cp_commit() { asm volatile("cp.async.commit_group;" ::: "memory"); }
__device__ __forceinline__ void cp_wait1() { asm volatile("cp.async.wait_group 1;" ::: "memory"); }
__device__ __forceinline__ void cp_wait0() { asm volatile("cp.async.wait_group 0;" ::: "memory"); }

__device__ __forceinline__ void ldmat4(uint32_t* r, uint32_t addr) {
    asm volatile("ldmatrix.sync.aligned.m8n8.x4.shared.b16 {%0,%1,%2,%3}, [%4];"
                 : "=r"(r[0]), "=r"(r[1]), "=r"(r[2]), "=r"(r[3]) : "r"(addr));
}
__device__ __forceinline__ void ldmat2(uint32_t* r, uint32_t addr) {
    asm volatile("ldmatrix.sync.aligned.m8n8.x2.shared.b16 {%0,%1}, [%2];"
                 : "=r"(r[0]), "=r"(r[1]) : "r"(addr));
}
__device__ __forceinline__ void mma_f16(float* c, const uint32_t* a, const uint32_t* b) {
    asm volatile("mma.sync.aligned.m16n8k16.row.col.f32.f16.f16.f32 "
                 "{%0,%1,%2,%3}, {%4,%5,%6,%7}, {%8,%9}, {%0,%1,%2,%3};"
                 : "+f"(c[0]), "+f"(c[1]), "+f"(c[2]), "+f"(c[3])
                 : "r"(a[0]), "r"(a[1]), "r"(a[2]), "r"(a[3]), "r"(b[0]), "r"(b[1]));
}
__device__ __forceinline__ float gelu_exact(float v) {
    return 0.5f * v * (1.0f + erff(v * 0.70710678118654752f));
}

// ---------------- init / gating / scatter ----------------------------------
__global__ void init_kernel() {
    int t = threadIdx.x;
    if (t < NE) { g_count[t] = 0; g_pos[t] = 0; }
    if (t == 0) g_zsum = 0.0f;
    if (t < NBz * NE) { g_proxy[t] = 0.0f; g_dens[t] = 0.0f; }
}

__global__ __launch_bounds__(256) void gate_kernel(
    const float* __restrict__ x, const float* __restrict__ Wg) {
    __shared__ float xs[DM];
    __shared__ float logits[NE];
    int t = blockIdx.x;
    const float* xr = x + (size_t)t * DM;
    for (int i = threadIdx.x; i < DM; i += blockDim.x) xs[i] = xr[i];
    __syncthreads();
    int w = threadIdx.x >> 5, lane = threadIdx.x & 31;
    const float* wg = Wg + w * DM;
    float s = 0.0f;
    for (int k = lane; k < DM; k += 32) s += xs[k] * wg[k];
#pragma unroll
    for (int o = 16; o; o >>= 1) s += __shfl_xor_sync(0xffffffffu, s, o);
    if (lane == 0) logits[w] = s;
    __syncthreads();
    if (threadIdx.x == 0) {
        float m = -1e30f;
#pragma unroll
        for (int e = 0; e < NE; e++) m = fmaxf(m, logits[e]);
        float p[NE], sum = 0.0f;
#pragma unroll
        for (int e = 0; e < NE; e++) { p[e] = expf(logits[e] - m); sum += p[e]; }
        float inv_sum = 1.0f / sum;
        float z = m + logf(sum);
        atomicAdd(&g_zsum, z * z);
        int b = t / NSz;
#pragma unroll
        for (int e = 0; e < NE; e++) atomicAdd(&g_proxy[b * NE + e], p[e] * inv_sum);
        int i0 = 0;
#pragma unroll
        for (int e = 1; e < NE; e++) if (p[e] > p[i0]) i0 = e;
        int i1 = (i0 == 0) ? 1 : 0;
#pragma unroll
        for (int e = 0; e < NE; e++) if (e != i0 && p[e] > p[i1]) i1 = e;
        atomicAdd(&g_dens[b * NE + i0], 1.0f);
        float v0 = p[i0], v1 = p[i1];
        float invw = 1.0f / (v0 + v1);
        g_wt[2 * t] = v0 * invw;
        g_wt[2 * t + 1] = v1 * invw;
        g_eid[2 * t] = i0;
        g_eid[2 * t + 1] = i1;
        atomicAdd(&g_count[i0], 1);
        atomicAdd(&g_count[i1], 1);
    }
}

__global__ void scan_kernel() {
    if (threadIdx.x == 0) {
        int acc = 0;
#pragma unroll
        for (int e = 0; e < NE; e++) { g_off[e] = acc; acc += g_count[e]; }
    }
}

__global__ void scatter_kernel() {
    int p = blockIdx.x * blockDim.x + threadIdx.x;
    if (p >= NP) return;
    int e = g_eid[p];
    int idx = atomicAdd(&g_pos[e], 1);
    g_order[g_off[e] + idx] = p;
}

// ---------------- conversions ----------------------------------------------
__global__ __launch_bounds__(256) void split_x_kernel(const float* __restrict__ x) {
    size_t i = (size_t)blockIdx.x * 256 + threadIdx.x;   // over NT*DM/4 float4s
    float4 v = ((const float4*)x)[i];
    __half h0 = __float2half_rn(v.x), h1 = __float2half_rn(v.y);
    __half h2 = __float2half_rn(v.z), h3 = __float2half_rn(v.w);
    __half l0 = __float2half_rn(v.x - __half2float(h0));
    __half l1 = __float2half_rn(v.y - __half2float(h1));
    __half l2 = __float2half_rn(v.z - __half2float(h2));
    __half l3 = __float2half_rn(v.w - __half2float(h3));
    ((__half2*)g_xhi)[2 * i]     = __half2(h0, h1);
    ((__half2*)g_xhi)[2 * i + 1] = __half2(h2, h3);
    ((__half2*)g_xlo)[2 * i]     = __half2(l0, l1);
    ((__half2*)g_xlo)[2 * i + 1] = __half2(l2, l3);
}

// transpose + convert:  wt[e][n][k] = fp16(W[e][k][n])
__global__ __launch_bounds__(256) void conv_w_kernel(
    const float* __restrict__ W1, const float* __restrict__ W2) {
    __shared__ float tile[32][33];
    int e = blockIdx.z & 7;
    int which = blockIdx.z >> 3;
    const float* W = which ? W2 : W1;
    __half* wh = which ? g_w2h : g_w1h;
    size_t base = (size_t)e * DM * DM;
    int n0 = blockIdx.x * 32, k0 = blockIdx.y * 32;
    int tx = threadIdx.x & 31, ty = threadIdx.x >> 5;  // 32 x 8
#pragma unroll
    for (int j = 0; j < 4; j++)
        tile[ty + 8 * j][tx] = W[base + (size_t)(k0 + ty + 8 * j) * DM + n0 + tx];
    __syncthreads();
#pragma unroll
    for (int j = 0; j < 4; j++) {
        float v = tile[tx][ty + 8 * j];
        wh[base + (size_t)(n0 + ty + 8 * j) * DM + k0 + tx] = __float2half_rn(v);
    }
}

// ---------------- HMMA GEMM (mma.sync fp16, A hi/lo split, 2 products) -----
// CTA tile 128x128, K chunk 32, 8 warps (2x4), warp tile 64x32, 3-stage cp.async
#define BM 128
#define BN 128
#define BK 32
#define NCHUNK (DM / BK)                 // 32
#define TSTRIDE 144                      // bytes per smem row (64B data + 80B pad)
#define TILE_BYTES (BM * TSTRIDE)        // 18432
#define ST_OFF(s)  ((s) * 3 * TILE_BYTES)
#define AHI_OFF(s) (ST_OFF(s))
#define ALO_OFF(s) (ST_OFF(s) + TILE_BYTES)
#define BMT_OFF(s) (ST_OFF(s) + 2 * TILE_BYTES)
#define TOKS_OFF   (3 * 3 * TILE_BYTES)  // 165888
#define PV_OFF     (TOKS_OFF + 512)
#define WV_OFF     (PV_OFF + 512)
#define SMEM_TOTAL (WV_OFF + 512)        // 167424

template <int PHASE>
__global__ __launch_bounds__(256, 1) void moe_gemm(const float* __restrict__ bias) {
    int e = blockIdx.z;
    int cnt = g_count[e];
    int row0 = blockIdx.x * BM;
    if (row0 >= cnt) return;
    int n0 = blockIdx.y * BN;
    int base = g_off[e];

    extern __shared__ char smem[];
    uint32_t sb = smem_u32(smem);
    int tid = threadIdx.x;
    int wid = tid >> 5, lane = tid & 31;
    int wr = wid >> 2, wc = wid & 3;      // 2 x 4 warp grid
    int m0w = wr * 64, n0w = wc * 32;

    int* toks = (int*)(smem + TOKS_OFF);
    if (tid < BM) {
        int r = row0 + tid;
        if (PHASE == 1) {
            toks[tid] = (r < cnt) ? (g_order[base + r] >> 1) : 0;
        } else {
            toks[tid] = (r < cnt) ? (base + r) : 0;
            int p = (r < cnt) ? g_order[base + r] : 0;
            ((int*)(smem + PV_OFF))[tid] = p;
            ((float*)(smem + WV_OFF))[tid] = g_wt[p];
        }
    }
    __syncthreads();

    const __half* Ahi = (PHASE == 1) ? g_xhi : g_hhi;
    const __half* Alo = (PHASE == 1) ? g_xlo : g_hlo;
    const __half* Wh  = ((PHASE == 1) ? g_w1h : g_w2h) + (size_t)e * DM * DM;

    float acc[4][4][4];
#pragma unroll
    for (int i = 0; i < 4; i++)
#pragma unroll
        for (int j = 0; j < 4; j++)
#pragma unroll
            for (int q = 0; q < 4; q++) acc[i][j][q] = 0.0f;

    auto load_chunk = [&](int c, int s) {
        int k0 = c * BK;
#pragma unroll
        for (int it = 0; it < 2; it++) {
            int i = tid + it * 256;          // 0..511
            int r = i >> 2, c16 = i & 3;
            uint32_t so = r * TSTRIDE + c16 * 16;
            size_t aoff = (size_t)toks[r] * DM + k0 + c16 * 8;
            size_t boff = (size_t)(n0 + r) * DM + k0 + c16 * 8;
            cp16(sb + AHI_OFF(s) + so, Ahi + aoff);
            cp16(sb + ALO_OFF(s) + so, Alo + aoff);
            cp16(sb + BMT_OFF(s) + so, Wh + boff);
        }
        cp_commit();
    };

    auto compute = [&](int s) {
#pragma unroll
        for (int kk = 0; kk < 2; kk++) {
            int kb = kk * 16;
            uint32_t ah[4][4], al[4][4], bm[4][2];
            int arow = m0w + (lane & 15);
            int acolb = (kb + ((lane & 16) ? 8 : 0)) * 2;
#pragma unroll
            for (int i = 0; i < 4; i++) {
                uint32_t addr = sb + AHI_OFF(s) + (arow + i * 16) * TSTRIDE + acolb;
                ldmat4(ah[i], addr);
                ldmat4(al[i], addr + TILE_BYTES);
            }
            int brow = lane & 7;
            int bcolb = (kb + ((lane & 8) ? 8 : 0)) * 2;
#pragma unroll
            for (int j = 0; j < 4; j++) {
                uint32_t addr = sb + BMT_OFF(s) + (n0w + j * 8 + brow) * TSTRIDE + bcolb;
                ldmat2(bm[j], addr);
            }
            // two product passes; 16 independent accumulators between reuses
#pragma unroll
            for (int i = 0; i < 4; i++)
#pragma unroll
                for (int j = 0; j < 4; j++) mma_f16(acc[i][j], ah[i], bm[j]);
#pragma unroll
            for (int i = 0; i < 4; i++)
#pragma unroll
                for (int j = 0; j < 4; j++) mma_f16(acc[i][j], al[i], bm[j]);
        }
    };

    load_chunk(0, 0);
    load_chunk(1, 1);
    for (int c = 0; c < NCHUNK; c++) {
        int s = c % 3;
        if (c < NCHUNK - 1) cp_wait1(); else cp_wait0();
        __syncthreads();
        if (c + 2 < NCHUNK) load_chunk(c + 2, (c + 2) % 3);
        compute(s);
    }

    // ---------------- epilogue ----------------
#pragma unroll
    for (int i = 0; i < 4; i++) {
        int rb = m0w + i * 16 + (lane >> 2);
#pragma unroll
        for (int j = 0; j < 4; j++) {
            int gcol = n0 + n0w + j * 8 + (lane & 3) * 2;
            float bv0 = bias[e * DM + gcol];
            float bv1 = bias[e * DM + gcol + 1];
#pragma unroll
            for (int h = 0; h < 2; h++) {
                int r = rb + h * 8;
                if (row0 + r >= cnt) continue;
                float v0 = acc[i][j][2 * h]     + bv0;
                float v1 = acc[i][j][2 * h + 1] + bv1;
                if (PHASE == 1) {
                    float gg0 = gelu_exact(v0), gg1 = gelu_exact(v1);
                    __half h0 = __float2half_rn(gg0);
                    __half h1 = __float2half_rn(gg1);
                    __half l0 = __float2half_rn(gg0 - __half2float(h0));
                    __half l1 = __float2half_rn(gg1 - __half2float(h1));
                    uint32_t hv = ((uint32_t)__half_as_ushort(h1) << 16) | __half_as_ushort(h0);
                    uint32_t lv = ((uint32_t)__half_as_ushort(l1) << 16) | __half_as_ushort(l0);
                    size_t o = (size_t)(base + row0 + r) * DM + gcol;
                    *(uint32_t*)(g_hhi + o) = hv;
                    *(uint32_t*)(g_hlo + o) = lv;
                } else {
                    float wv = ((float*)(smem + WV_OFF))[r];
                    int p = ((int*)(smem + PV_OFF))[r];
                    float2 v = make_float2(v0 * wv, v1 * wv);
                    *(float2*)(g_y + (size_t)p * DM + gcol) = v;
                }
            }
        }
    }
}

// ---------------- combine + losses -----------------------------------------
__global__ __launch_bounds__(256) void combine_kernel(float* __restrict__ out) {
    size_t i = (size_t)blockIdx.x * 256 + threadIdx.x;  // over NT*DM/4 float4s
    size_t t = i >> 8, c = i & 255;
    const float4* y4 = (const float4*)g_y;
    float4 a = y4[(2 * t) * (DM / 4) + c];
    float4 b = y4[(2 * t + 1) * (DM / 4) + c];
    float4 o;
    o.x = a.x + b.x; o.y = a.y + b.y; o.z = a.z + b.z; o.w = a.w + b.w;
    ((float4*)out)[t * (DM / 4) + c] = o;
}

__global__ void finalize_kernel(float* __restrict__ out) {
    if (threadIdx.x == 0) {
        float zloss = g_zsum / (float)NT;
        float bal = 0.0f;
#pragma unroll
        for (int i = 0; i < NBz * NE; i++)
            bal += (g_proxy[i] / (float)NSz) * (g_dens[i] / (float)NSz);
        bal = bal / (float)(NBz * NE) * (float)(NE * NE);
        out[(size_t)NT * DM]     = bal * 0.01f + zloss * 0.001f;
        out[(size_t)NT * DM + 1] = bal;
    }
}

// ---------------- launch ----------------------------------------------------
extern "C" void kernel_launch(void* const* d_in, const int* in_sizes, int n_in,
                              void* d_out, int out_size) {
    const float* x  = (const float*)d_in[0];
    const float* Wg = (const float*)d_in[1];
    const float* W1 = (const float*)d_in[2];
    const float* b1 = (const float*)d_in[3];
    const float* W2 = (const float*)d_in[4];
    const float* b2 = (const float*)d_in[5];
    float* out = (float*)d_out;

    cudaFuncSetAttribute(moe_gemm<1>, cudaFuncAttributeMaxDynamicSharedMemorySize, SMEM_TOTAL);
    cudaFuncSetAttribute(moe_gemm<2>, cudaFuncAttributeMaxDynamicSharedMemorySize, SMEM_TOTAL);

    init_kernel<<<1, 32>>>();
    gate_kernel<<<NT, 256>>>(x, Wg);
    scan_kernel<<<1, 32>>>();
    scatter_kernel<<<NP / 256, 256>>>();
    split_x_kernel<<<NT * DM / 4 / 256, 256>>>(x);
    conv_w_kernel<<<dim3(32, 32, 16), 256>>>(W1, W2);

    dim3 ggrid(64, 8, NE);
    moe_gemm<1><<<ggrid, 256, SMEM_TOTAL>>>(b1);
    moe_gemm<2><<<ggrid, 256, SMEM_TOTAL>>>(b2);
    combine_kernel<<<NT * DM / 4 / 256, 256>>>(out);
    finalize_kernel<<<1, 32>>>(out);
}

// round 7
// speedup vs baseline: 3.7362x; 1.2842x over previous
#include <cuda_runtime.h>
#include <cuda_fp16.h>
#include <math.h>
#include <stdint.h>

#define NE 8
#define DM 1024
#define NBz 4
#define NSz 2048
#define NT 8192           // tokens
#define NP 16384          // (token,slot) pairs

// ---------------- device scratch (no allocation allowed) -------------------
__device__ __align__(1024) __half g_xh[(size_t)NT * DM];
__device__ __align__(1024) __half g_w1h[(size_t)NE * DM * DM];   // natural [e][k][n]
__device__ __align__(1024) __half g_w2h[(size_t)NE * DM * DM];
__device__ __align__(1024) __half g_hh[(size_t)NP * DM];
__device__ __align__(1024) float g_y[(size_t)NP * DM];
__device__ int   g_order[NP];
__device__ float g_wt[NP];
__device__ int   g_eid[NP];
__device__ int   g_count[NE], g_off[NE], g_pos[NE];
__device__ float g_zsum, g_proxy[NBz * NE], g_dens[NBz * NE];

// ---------------- helpers ---------------------------------------------------
__device__ __forceinline__ uint32_t smem_u32(const void* p) {
    uint32_t a;
    asm("{ .reg .u64 t; cvta.to.shared.u64 t, %1; cvt.u32.u64 %0, t; }" : "=r"(a) : "l"(p));
    return a;
}
__device__ __forceinline__ void cp16(uint32_t dst, const void* src) {
    asm volatile("cp.async.cg.shared.global [%0], [%1], 16;" :: "r"(dst), "l"(src));
}
__device__ __forceinline__ void cp_commit() { asm volatile("cp.async.commit_group;" ::: "memory"); }
__device__ __forceinline__ void cp_wait1() { asm volatile("cp.async.wait_group 1;" ::: "memory"); }
__device__ __forceinline__ void cp_wait0() { asm volatile("cp.async.wait_group 0;" ::: "memory"); }

__device__ __forceinline__ void ldmat4(uint32_t* r, uint32_t addr) {
    asm volatile("ldmatrix.sync.aligned.m8n8.x4.shared.b16 {%0,%1,%2,%3}, [%4];"
                 : "=r"(r[0]), "=r"(r[1]), "=r"(r[2]), "=r"(r[3]) : "r"(addr));
}
__device__ __forceinline__ void ldmat2t(uint32_t* r, uint32_t addr) {
    asm volatile("ldmatrix.sync.aligned.m8n8.x2.trans.shared.b16 {%0,%1}, [%2];"
                 : "=r"(r[0]), "=r"(r[1]) : "r"(addr));
}
__device__ __forceinline__ void mma_f16(float* c, const uint32_t* a, const uint32_t* b) {
    asm volatile("mma.sync.aligned.m16n8k16.row.col.f32.f16.f16.f32 "
                 "{%0,%1,%2,%3}, {%4,%5,%6,%7}, {%8,%9}, {%0,%1,%2,%3};"
                 : "+f"(c[0]), "+f"(c[1]), "+f"(c[2]), "+f"(c[3])
                 : "r"(a[0]), "r"(a[1]), "r"(a[2]), "r"(a[3]), "r"(b[0]), "r"(b[1]));
}
__device__ __forceinline__ float gelu_exact(float v) {
    return 0.5f * v * (1.0f + erff(v * 0.70710678118654752f));
}

// ---------------- init / gating / scatter ----------------------------------
__global__ void init_kernel() {
    int t = threadIdx.x;
    if (t < NE) { g_count[t] = 0; g_pos[t] = 0; }
    if (t == 0) g_zsum = 0.0f;
    if (t < NBz * NE) { g_proxy[t] = 0.0f; g_dens[t] = 0.0f; }
}

// gating + fp16 conversion of x (x already staged in smem)
__global__ __launch_bounds__(256) void gate_kernel(
    const float* __restrict__ x, const float* __restrict__ Wg) {
    __shared__ float xs[DM];
    __shared__ float logits[NE];
    int t = blockIdx.x;
    const float* xr = x + (size_t)t * DM;
    for (int i = threadIdx.x; i < DM; i += blockDim.x) xs[i] = xr[i];
    __syncthreads();
    // fp16 copy of x
    for (int i = threadIdx.x; i < DM / 2; i += blockDim.x) {
        __half2 v = __half2(__float2half_rn(xs[2 * i]), __float2half_rn(xs[2 * i + 1]));
        ((__half2*)(g_xh + (size_t)t * DM))[i] = v;
    }
    int w = threadIdx.x >> 5, lane = threadIdx.x & 31;
    const float* wg = Wg + w * DM;
    float s = 0.0f;
    for (int k = lane; k < DM; k += 32) s += xs[k] * wg[k];
#pragma unroll
    for (int o = 16; o; o >>= 1) s += __shfl_xor_sync(0xffffffffu, s, o);
    if (lane == 0) logits[w] = s;
    __syncthreads();
    if (threadIdx.x == 0) {
        float m = -1e30f;
#pragma unroll
        for (int e = 0; e < NE; e++) m = fmaxf(m, logits[e]);
        float p[NE], sum = 0.0f;
#pragma unroll
        for (int e = 0; e < NE; e++) { p[e] = expf(logits[e] - m); sum += p[e]; }
        float inv_sum = 1.0f / sum;
        float z = m + logf(sum);
        atomicAdd(&g_zsum, z * z);
        int b = t / NSz;
#pragma unroll
        for (int e = 0; e < NE; e++) atomicAdd(&g_proxy[b * NE + e], p[e] * inv_sum);
        int i0 = 0;
#pragma unroll
        for (int e = 1; e < NE; e++) if (p[e] > p[i0]) i0 = e;
        int i1 = (i0 == 0) ? 1 : 0;
#pragma unroll
        for (int e = 0; e < NE; e++) if (e != i0 && p[e] > p[i1]) i1 = e;
        atomicAdd(&g_dens[b * NE + i0], 1.0f);
        float v0 = p[i0], v1 = p[i1];
        float invw = 1.0f / (v0 + v1);
        g_wt[2 * t] = v0 * invw;
        g_wt[2 * t + 1] = v1 * invw;
        g_eid[2 * t] = i0;
        g_eid[2 * t + 1] = i1;
        atomicAdd(&g_count[i0], 1);
        atomicAdd(&g_count[i1], 1);
    }
}

__global__ void scan_kernel() {
    if (threadIdx.x == 0) {
        int acc = 0;
#pragma unroll
        for (int e = 0; e < NE; e++) { g_off[e] = acc; acc += g_count[e]; }
    }
}

__global__ void scatter_kernel() {
    int p = blockIdx.x * blockDim.x + threadIdx.x;
    if (p >= NP) return;
    int e = g_eid[p];
    int idx = atomicAdd(&g_pos[e], 1);
    g_order[g_off[e] + idx] = p;
}

// ---------------- weight convert (no transpose; natural layout) ------------
__global__ __launch_bounds__(256) void conv_w_kernel(
    const float* __restrict__ W1, const float* __restrict__ W2) {
    const float* W = blockIdx.y ? W2 : W1;
    __half* wh = blockIdx.y ? g_w2h : g_w1h;
    size_t i = (size_t)blockIdx.x * 256 + threadIdx.x;   // over NE*DM*DM/4 float4s
    float4 v = ((const float4*)W)[i];
    __half2 a = __half2(__float2half_rn(v.x), __float2half_rn(v.y));
    __half2 b = __half2(__float2half_rn(v.z), __float2half_rn(v.w));
    ((__half2*)wh)[2 * i] = a;
    ((__half2*)wh)[2 * i + 1] = b;
}

// ---------------- HMMA GEMM (single fp16 product) --------------------------
// CTA tile 128x128, K chunk 32, 8 warps (2x4), warp tile 64x32, 3-stage cp.async
#define BM 128
#define BN 128
#define BK 32
#define NCHUNK (DM / BK)                 // 32
#define ASTRIDE 80                       // 64B data + 16B pad (conflict-free ldmatrix)
#define BSTRIDE 272                      // 256B data + 16B pad
#define A_BYTES (BM * ASTRIDE)           // 10240
#define B_BYTES (BK * BSTRIDE)           // 8704
#define STAGE_BYTES (A_BYTES + B_BYTES)  // 18944
#define A_OFF(s) ((s) * STAGE_BYTES)
#define B_OFF(s) ((s) * STAGE_BYTES + A_BYTES)
#define TOKS_OFF (3 * STAGE_BYTES)       // 56832
#define PV_OFF   (TOKS_OFF + 512)
#define WV_OFF   (PV_OFF + 512)
#define SMEM_TOTAL (WV_OFF + 512)        // 58368

template <int PHASE>
__global__ __launch_bounds__(256, 2) void moe_gemm(const float* __restrict__ bias) {
    int e = blockIdx.z;
    int cnt = g_count[e];
    int row0 = blockIdx.x * BM;
    if (row0 >= cnt) return;
    int n0 = blockIdx.y * BN;
    int base = g_off[e];

    extern __shared__ char smem[];
    uint32_t sb = smem_u32(smem);
    int tid = threadIdx.x;
    int wid = tid >> 5, lane = tid & 31;
    int wr = wid >> 2, wc = wid & 3;      // 2 x 4 warp grid
    int m0w = wr * 64, n0w = wc * 32;

    int* toks = (int*)(smem + TOKS_OFF);
    if (tid < BM) {
        int r = row0 + tid;
        if (PHASE == 1) {
            toks[tid] = (r < cnt) ? (g_order[base + r] >> 1) : 0;
        } else {
            toks[tid] = (r < cnt) ? (base + r) : 0;
            int p = (r < cnt) ? g_order[base + r] : 0;
            ((int*)(smem + PV_OFF))[tid] = p;
            ((float*)(smem + WV_OFF))[tid] = g_wt[p];
        }
    }
    __syncthreads();

    const __half* Ah = (PHASE == 1) ? g_xh : g_hh;
    const __half* Wh = ((PHASE == 1) ? g_w1h : g_w2h) + (size_t)e * DM * DM;

    float acc[4][4][4];
#pragma unroll
    for (int i = 0; i < 4; i++)
#pragma unroll
        for (int j = 0; j < 4; j++)
#pragma unroll
            for (int q = 0; q < 4; q++) acc[i][j][q] = 0.0f;

    auto load_chunk = [&](int c, int s) {
        int k0 = c * BK;
        // A: 128 rows x 64B = 512 cp16
#pragma unroll
        for (int it = 0; it < 2; it++) {
            int i = tid + it * 256;
            int r = i >> 2, cq = i & 3;
            cp16(sb + A_OFF(s) + r * ASTRIDE + cq * 16,
                 Ah + (size_t)toks[r] * DM + k0 + cq * 8);
        }
        // B: 32 k-rows x 256B = 512 cp16 (natural W[k][n] layout)
#pragma unroll
        for (int it = 0; it < 2; it++) {
            int i = tid + it * 256;
            int k = i >> 4, cq = i & 15;
            cp16(sb + B_OFF(s) + k * BSTRIDE + cq * 16,
                 Wh + (size_t)(k0 + k) * DM + n0 + cq * 8);
        }
        cp_commit();
    };

    auto compute = [&](int s) {
#pragma unroll
        for (int kk = 0; kk < 2; kk++) {
            int kb = kk * 16;
            uint32_t a[4][4], b[4][2];
            int arow = m0w + (lane & 15);
            int acolb = (kb + ((lane & 16) ? 8 : 0)) * 2;
#pragma unroll
            for (int i = 0; i < 4; i++)
                ldmat4(a[i], sb + A_OFF(s) + (arow + i * 16) * ASTRIDE + acolb);
            int brow = kb + (lane & 15);
#pragma unroll
            for (int j = 0; j < 4; j++)
                ldmat2t(b[j], sb + B_OFF(s) + brow * BSTRIDE + (n0w + j * 8) * 2);
#pragma unroll
            for (int i = 0; i < 4; i++)
#pragma unroll
                for (int j = 0; j < 4; j++) mma_f16(acc[i][j], a[i], b[j]);
        }
    };

    load_chunk(0, 0);
    load_chunk(1, 1);
    for (int c = 0; c < NCHUNK; c++) {
        int s = c % 3;
        if (c < NCHUNK - 1) cp_wait1(); else cp_wait0();
        __syncthreads();
        if (c + 2 < NCHUNK) load_chunk(c + 2, (c + 2) % 3);
        compute(s);
    }

    // ---------------- epilogue ----------------
#pragma unroll
    for (int i = 0; i < 4; i++) {
        int rb = m0w + i * 16 + (lane >> 2);
#pragma unroll
        for (int j = 0; j < 4; j++) {
            int gcol = n0 + n0w + j * 8 + (lane & 3) * 2;
            float bv0 = bias[e * DM + gcol];
            float bv1 = bias[e * DM + gcol + 1];
#pragma unroll
            for (int h = 0; h < 2; h++) {
                int r = rb + h * 8;
                if (row0 + r >= cnt) continue;
                float v0 = acc[i][j][2 * h]     + bv0;
                float v1 = acc[i][j][2 * h + 1] + bv1;
                if (PHASE == 1) {
                    float gg0 = gelu_exact(v0), gg1 = gelu_exact(v1);
                    __half2 hv = __half2(__float2half_rn(gg0), __float2half_rn(gg1));
                    size_t o = (size_t)(base + row0 + r) * DM + gcol;
                    *(__half2*)(g_hh + o) = hv;
                } else {
                    float wv = ((float*)(smem + WV_OFF))[r];
                    int p = ((int*)(smem + PV_OFF))[r];
                    float2 v = make_float2(v0 * wv, v1 * wv);
                    *(float2*)(g_y + (size_t)p * DM + gcol) = v;
                }
            }
        }
    }
}

// ---------------- combine + losses -----------------------------------------
__global__ __launch_bounds__(256) void combine_kernel(float* __restrict__ out) {
    size_t i = (size_t)blockIdx.x * 256 + threadIdx.x;  // over NT*DM/4 float4s
    size_t t = i >> 8, c = i & 255;
    const float4* y4 = (const float4*)g_y;
    float4 a = y4[(2 * t) * (DM / 4) + c];
    float4 b = y4[(2 * t + 1) * (DM / 4) + c];
    float4 o;
    o.x = a.x + b.x; o.y = a.y + b.y; o.z = a.z + b.z; o.w = a.w + b.w;
    ((float4*)out)[t * (DM / 4) + c] = o;
}

__global__ void finalize_kernel(float* __restrict__ out) {
    if (threadIdx.x == 0) {
        float zloss = g_zsum / (float)NT;
        float bal = 0.0f;
#pragma unroll
        for (int i = 0; i < NBz * NE; i++)
            bal += (g_proxy[i] / (float)NSz) * (g_dens[i] / (float)NSz);
        bal = bal / (float)(NBz * NE) * (float)(NE * NE);
        out[(size_t)NT * DM]     = bal * 0.01f + zloss * 0.001f;
        out[(size_t)NT * DM + 1] = bal;
    }
}

// ---------------- launch ----------------------------------------------------
extern "C" void kernel_launch(void* const* d_in, const int* in_sizes, int n_in,
                              void* d_out, int out_size) {
    const float* x  = (const float*)d_in[0];
    const float* Wg = (const float*)d_in[1];
    const float* W1 = (const float*)d_in[2];
    const float* b1 = (const float*)d_in[3];
    const float* W2 = (const float*)d_in[4];
    const float* b2 = (const float*)d_in[5];
    float* out = (float*)d_out;

    cudaFuncSetAttribute(moe_gemm<1>, cudaFuncAttributeMaxDynamicSharedMemorySize, SMEM_TOTAL);
    cudaFuncSetAttribute(moe_gemm<2>, cudaFuncAttributeMaxDynamicSharedMemorySize, SMEM_TOTAL);

    init_kernel<<<1, 32>>>();
    gate_kernel<<<NT, 256>>>(x, Wg);
    scan_kernel<<<1, 32>>>();
    scatter_kernel<<<NP / 256, 256>>>();
    conv_w_kernel<<<dim3((unsigned)((size_t)NE * DM * DM / 4 / 256), 2), 256>>>(W1, W2);

    dim3 ggrid(64, 8, NE);
    moe_gemm<1><<<ggrid, 256, SMEM_TOTAL>>>(b1);
    moe_gemm<2><<<ggrid, 256, SMEM_TOTAL>>>(b2);
    combine_kernel<<<NT * DM / 4 / 256, 256>>>(out);
    finalize_kernel<<<1, 32>>>(out);
}

// round 8
// speedup vs baseline: 5.0131x; 1.3418x over previous
#include <cuda_runtime.h>
#include <cuda_fp16.h>
#include <math.h>
#include <stdint.h>

#define NE 8
#define DM 1024
#define NBz 4
#define NSz 2048
#define NT 8192           // tokens
#define NP 16384          // (token,slot) pairs

// ---------------- device scratch (no allocation allowed) -------------------
__device__ __align__(1024) __half g_xh[(size_t)NT * DM];
__device__ __align__(1024) __half g_w1h[(size_t)NE * DM * DM];   // natural [e][k][n]
__device__ __align__(1024) __half g_w2h[(size_t)NE * DM * DM];
__device__ __align__(1024) __half g_hh[(size_t)NP * DM];
__device__ __align__(1024) float g_y[(size_t)NP * DM];
__device__ int   g_order[NP];
__device__ float g_wt[NP];
__device__ int   g_eid[NP];
__device__ int   g_count[NE], g_off[NE], g_pos[NE];
__device__ int   g_toff[NE + 1];
__device__ float g_zsum, g_proxy[NBz * NE], g_dens[NBz * NE];

// ---------------- helpers ---------------------------------------------------
__device__ __forceinline__ uint32_t smem_u32(const void* p) {
    uint32_t a;
    asm("{ .reg .u64 t; cvta.to.shared.u64 t, %1; cvt.u32.u64 %0, t; }" : "=r"(a) : "l"(p));
    return a;
}
__device__ __forceinline__ void cp16(uint32_t dst, const void* src) {
    asm volatile("cp.async.cg.shared.global [%0], [%1], 16;" :: "r"(dst), "l"(src));
}
__device__ __forceinline__ void cp_commit() { asm volatile("cp.async.commit_group;" ::: "memory"); }
__device__ __forceinline__ void cp_wait1() { asm volatile("cp.async.wait_group 1;" ::: "memory"); }
__device__ __forceinline__ void cp_wait0() { asm volatile("cp.async.wait_group 0;" ::: "memory"); }

__device__ __forceinline__ void ldmat4(uint32_t* r, uint32_t addr) {
    asm volatile("ldmatrix.sync.aligned.m8n8.x4.shared.b16 {%0,%1,%2,%3}, [%4];"
                 : "=r"(r[0]), "=r"(r[1]), "=r"(r[2]), "=r"(r[3]) : "r"(addr));
}
__device__ __forceinline__ void ldmat2t(uint32_t* r, uint32_t addr) {
    asm volatile("ldmatrix.sync.aligned.m8n8.x2.trans.shared.b16 {%0,%1}, [%2];"
                 : "=r"(r[0]), "=r"(r[1]) : "r"(addr));
}
__device__ __forceinline__ void mma_f16(float* c, const uint32_t* a, const uint32_t* b) {
    asm volatile("mma.sync.aligned.m16n8k16.row.col.f32.f16.f16.f32 "
                 "{%0,%1,%2,%3}, {%4,%5,%6,%7}, {%8,%9}, {%0,%1,%2,%3};"
                 : "+f"(c[0]), "+f"(c[1]), "+f"(c[2]), "+f"(c[3])
                 : "r"(a[0]), "r"(a[1]), "r"(a[2]), "r"(a[3]), "r"(b[0]), "r"(b[1]));
}
__device__ __forceinline__ float gelu_exact(float v) {
    return 0.5f * v * (1.0f + erff(v * 0.70710678118654752f));
}

// ---------------- init / gating / scatter ----------------------------------
__global__ void init_kernel() {
    int t = threadIdx.x;
    if (t < NE) { g_count[t] = 0; g_pos[t] = 0; }
    if (t == 0) g_zsum = 0.0f;
    if (t < NBz * NE) { g_proxy[t] = 0.0f; g_dens[t] = 0.0f; }
}

// gating + fp16 conversion of x (x already staged in smem)
__global__ __launch_bounds__(256) void gate_kernel(
    const float* __restrict__ x, const float* __restrict__ Wg) {
    __shared__ float xs[DM];
    __shared__ float logits[NE];
    int t = blockIdx.x;
    const float* xr = x + (size_t)t * DM;
    for (int i = threadIdx.x; i < DM; i += blockDim.x) xs[i] = xr[i];
    __syncthreads();
    for (int i = threadIdx.x; i < DM / 2; i += blockDim.x) {
        __half2 v = __half2(__float2half_rn(xs[2 * i]), __float2half_rn(xs[2 * i + 1]));
        ((__half2*)(g_xh + (size_t)t * DM))[i] = v;
    }
    int w = threadIdx.x >> 5, lane = threadIdx.x & 31;
    const float* wg = Wg + w * DM;
    float s = 0.0f;
    for (int k = lane; k < DM; k += 32) s += xs[k] * wg[k];
#pragma unroll
    for (int o = 16; o; o >>= 1) s += __shfl_xor_sync(0xffffffffu, s, o);
    if (lane == 0) logits[w] = s;
    __syncthreads();
    if (threadIdx.x == 0) {
        float m = -1e30f;
#pragma unroll
        for (int e = 0; e < NE; e++) m = fmaxf(m, logits[e]);
        float p[NE], sum = 0.0f;
#pragma unroll
        for (int e = 0; e < NE; e++) { p[e] = expf(logits[e] - m); sum += p[e]; }
        float inv_sum = 1.0f / sum;
        float z = m + logf(sum);
        atomicAdd(&g_zsum, z * z);
        int b = t / NSz;
#pragma unroll
        for (int e = 0; e < NE; e++) atomicAdd(&g_proxy[b * NE + e], p[e] * inv_sum);
        int i0 = 0;
#pragma unroll
        for (int e = 1; e < NE; e++) if (p[e] > p[i0]) i0 = e;
        int i1 = (i0 == 0) ? 1 : 0;
#pragma unroll
        for (int e = 0; e < NE; e++) if (e != i0 && p[e] > p[i1]) i1 = e;
        atomicAdd(&g_dens[b * NE + i0], 1.0f);
        float v0 = p[i0], v1 = p[i1];
        float invw = 1.0f / (v0 + v1);
        g_wt[2 * t] = v0 * invw;
        g_wt[2 * t + 1] = v1 * invw;
        g_eid[2 * t] = i0;
        g_eid[2 * t + 1] = i1;
        atomicAdd(&g_count[i0], 1);
        atomicAdd(&g_count[i1], 1);
    }
}

__global__ void scan_kernel() {
    if (threadIdx.x == 0) {
        int acc = 0, tacc = 0;
#pragma unroll
        for (int e = 0; e < NE; e++) {
            g_off[e] = acc;
            g_toff[e] = tacc;
            acc += g_count[e];
            tacc += ((g_count[e] + 127) >> 7) * 8;   // rowtiles * n-tiles
        }
        g_toff[NE] = tacc;
    }
}

__global__ void scatter_kernel() {
    int p = blockIdx.x * blockDim.x + threadIdx.x;
    if (p >= NP) return;
    int e = g_eid[p];
    int idx = atomicAdd(&g_pos[e], 1);
    g_order[g_off[e] + idx] = p;
}

// ---------------- weight convert (no transpose; natural layout) ------------
__global__ __launch_bounds__(256) void conv_w_kernel(
    const float* __restrict__ W1, const float* __restrict__ W2) {
    const float* W = blockIdx.y ? W2 : W1;
    __half* wh = blockIdx.y ? g_w2h : g_w1h;
    size_t i = (size_t)blockIdx.x * 256 + threadIdx.x;   // over NE*DM*DM/4 float4s
    float4 v = ((const float4*)W)[i];
    __half2 a = __half2(__float2half_rn(v.x), __float2half_rn(v.y));
    __half2 b = __half2(__float2half_rn(v.z), __float2half_rn(v.w));
    ((__half2*)wh)[2 * i] = a;
    ((__half2*)wh)[2 * i + 1] = b;
}

// ---------------- HMMA GEMM (single fp16 product, persistent tiles) --------
// CTA tile 128x128, K chunk 64, 8 warps (2x4), warp tile 64x32, 3-stage cp.async
#define BM 128
#define BN 128
#define BK 64
#define NCHUNK (DM / BK)                 // 16
#define ASTRIDE 144                      // 128B data + 16B pad
#define BSTRIDE 272                      // 256B data + 16B pad
#define A_BYTES (BM * ASTRIDE)           // 18432
#define B_BYTES (BK * BSTRIDE)           // 17408
#define STAGE_BYTES (A_BYTES + B_BYTES)  // 35840
#define A_OFF(s) ((s) * STAGE_BYTES)
#define B_OFF(s) ((s) * STAGE_BYTES + A_BYTES)
#define TOKS_OFF (3 * STAGE_BYTES)       // 107520
#define PV_OFF   (TOKS_OFF + 512)
#define WV_OFF   (PV_OFF + 512)
#define SMEM_TOTAL (WV_OFF + 512)        // 109056
#define NGEMM_CTAS 296

template <int PHASE>
__global__ __launch_bounds__(256, 2) void moe_gemm(const float* __restrict__ bias) {
    extern __shared__ char smem[];
    uint32_t sb = smem_u32(smem);
    int tid = threadIdx.x;
    int wid = tid >> 5, lane = tid & 31;
    int wr = wid >> 2, wc = wid & 3;      // 2 x 4 warp grid
    int m0w = wr * 64, n0w = wc * 32;

    int* toks = (int*)(smem + TOKS_OFF);
    int ntiles = g_toff[NE];

    for (int t = blockIdx.x; t < ntiles; t += NGEMM_CTAS) {
        // decode tile -> (expert, row tile, n tile)
        int e = 0;
#pragma unroll
        for (int k = 1; k < NE; k++) if (t >= g_toff[k]) e = k;
        int tl = t - g_toff[e];
        int row0 = (tl >> 3) * BM;
        int n0 = (tl & 7) * BN;
        int cnt = g_count[e];
        int base = g_off[e];

        __syncthreads();   // previous tile's epilogue smem reads done
        if (tid < BM) {
            int r = row0 + tid;
            if (PHASE == 1) {
                toks[tid] = (r < cnt) ? (g_order[base + r] >> 1) : 0;
            } else {
                toks[tid] = (r < cnt) ? (base + r) : 0;
                int p = (r < cnt) ? g_order[base + r] : 0;
                ((int*)(smem + PV_OFF))[tid] = p;
                ((float*)(smem + WV_OFF))[tid] = g_wt[p];
            }
        }
        __syncthreads();

        const __half* Ah = (PHASE == 1) ? g_xh : g_hh;
        const __half* Wh = ((PHASE == 1) ? g_w1h : g_w2h) + (size_t)e * DM * DM;

        float acc[4][4][4];
#pragma unroll
        for (int i = 0; i < 4; i++)
#pragma unroll
            for (int j = 0; j < 4; j++)
#pragma unroll
                for (int q = 0; q < 4; q++) acc[i][j][q] = 0.0f;

        auto load_chunk = [&](int c, int s) {
            int k0 = c * BK;
            // A: 128 rows x 128B = 1024 cp16
#pragma unroll
            for (int it = 0; it < 4; it++) {
                int i = tid + it * 256;
                int r = i >> 3, cq = i & 7;
                cp16(sb + A_OFF(s) + r * ASTRIDE + cq * 16,
                     Ah + (size_t)toks[r] * DM + k0 + cq * 8);
            }
            // B: 64 k-rows x 256B = 1024 cp16
#pragma unroll
            for (int it = 0; it < 4; it++) {
                int i = tid + it * 256;
                int k = i >> 4, cq = i & 15;
                cp16(sb + B_OFF(s) + k * BSTRIDE + cq * 16,
                     Wh + (size_t)(k0 + k) * DM + n0 + cq * 8);
            }
            cp_commit();
        };

        auto compute = [&](int s) {
#pragma unroll
            for (int kk = 0; kk < 4; kk++) {
                int kb = kk * 16;
                uint32_t a[4][4], b[4][2];
                int arow = m0w + (lane & 15);
                int acolb = (kb + ((lane & 16) ? 8 : 0)) * 2;
#pragma unroll
                for (int i = 0; i < 4; i++)
                    ldmat4(a[i], sb + A_OFF(s) + (arow + i * 16) * ASTRIDE + acolb);
                int brow = kb + (lane & 15);
#pragma unroll
                for (int j = 0; j < 4; j++)
                    ldmat2t(b[j], sb + B_OFF(s) + brow * BSTRIDE + (n0w + j * 8) * 2);
#pragma unroll
                for (int i = 0; i < 4; i++)
#pragma unroll
                    for (int j = 0; j < 4; j++) mma_f16(acc[i][j], a[i], b[j]);
            }
        };

        load_chunk(0, 0);
        load_chunk(1, 1);
        for (int c = 0; c < NCHUNK; c++) {
            int s = c % 3;
            if (c < NCHUNK - 1) cp_wait1(); else cp_wait0();
            __syncthreads();
            if (c + 2 < NCHUNK) load_chunk(c + 2, (c + 2) % 3);
            compute(s);
        }

        // ---------------- epilogue ----------------
#pragma unroll
        for (int i = 0; i < 4; i++) {
            int rb = m0w + i * 16 + (lane >> 2);
#pragma unroll
            for (int j = 0; j < 4; j++) {
                int gcol = n0 + n0w + j * 8 + (lane & 3) * 2;
                float bv0 = bias[e * DM + gcol];
                float bv1 = bias[e * DM + gcol + 1];
#pragma unroll
                for (int h = 0; h < 2; h++) {
                    int r = rb + h * 8;
                    if (row0 + r >= cnt) continue;
                    float v0 = acc[i][j][2 * h]     + bv0;
                    float v1 = acc[i][j][2 * h + 1] + bv1;
                    if (PHASE == 1) {
                        float gg0 = gelu_exact(v0), gg1 = gelu_exact(v1);
                        __half2 hv = __half2(__float2half_rn(gg0), __float2half_rn(gg1));
                        size_t o = (size_t)(base + row0 + r) * DM + gcol;
                        *(__half2*)(g_hh + o) = hv;
                    } else {
                        float wv = ((float*)(smem + WV_OFF))[r];
                        int p = ((int*)(smem + PV_OFF))[r];
                        float2 v = make_float2(v0 * wv, v1 * wv);
                        *(float2*)(g_y + (size_t)p * DM + gcol) = v;
                    }
                }
            }
        }
    }
}

// ---------------- combine + losses -----------------------------------------
__global__ __launch_bounds__(256) void combine_kernel(float* __restrict__ out) {
    size_t i = (size_t)blockIdx.x * 256 + threadIdx.x;  // over NT*DM/4 float4s
    size_t t = i >> 8, c = i & 255;
    const float4* y4 = (const float4*)g_y;
    float4 a = y4[(2 * t) * (DM / 4) + c];
    float4 b = y4[(2 * t + 1) * (DM / 4) + c];
    float4 o;
    o.x = a.x + b.x; o.y = a.y + b.y; o.z = a.z + b.z; o.w = a.w + b.w;
    ((float4*)out)[t * (DM / 4) + c] = o;
}

__global__ void finalize_kernel(float* __restrict__ out) {
    if (threadIdx.x == 0) {
        float zloss = g_zsum / (float)NT;
        float bal = 0.0f;
#pragma unroll
        for (int i = 0; i < NBz * NE; i++)
            bal += (g_proxy[i] / (float)NSz) * (g_dens[i] / (float)NSz);
        bal = bal / (float)(NBz * NE) * (float)(NE * NE);
        out[(size_t)NT * DM]     = bal * 0.01f + zloss * 0.001f;
        out[(size_t)NT * DM + 1] = bal;
    }
}

// ---------------- launch ----------------------------------------------------
extern "C" void kernel_launch(void* const* d_in, const int* in_sizes, int n_in,
                              void* d_out, int out_size) {
    const float* x  = (const float*)d_in[0];
    const float* Wg = (const float*)d_in[1];
    const float* W1 = (const float*)d_in[2];
    const float* b1 = (const float*)d_in[3];
    const float* W2 = (const float*)d_in[4];
    const float* b2 = (const float*)d_in[5];
    float* out = (float*)d_out;

    cudaFuncSetAttribute(moe_gemm<1>, cudaFuncAttributeMaxDynamicSharedMemorySize, SMEM_TOTAL);
    cudaFuncSetAttribute(moe_gemm<2>, cudaFuncAttributeMaxDynamicSharedMemorySize, SMEM_TOTAL);

    init_kernel<<<1, 32>>>();
    gate_kernel<<<NT, 256>>>(x, Wg);
    scan_kernel<<<1, 32>>>();
    scatter_kernel<<<NP / 256, 256>>>();
    conv_w_kernel<<<dim3((unsigned)((size_t)NE * DM * DM / 4 / 256), 2), 256>>>(W1, W2);

    moe_gemm<1><<<NGEMM_CTAS, 256, SMEM_TOTAL>>>(b1);
    moe_gemm<2><<<NGEMM_CTAS, 256, SMEM_TOTAL>>>(b2);
    combine_kernel<<<NT * DM / 4 / 256, 256>>>(out);
    finalize_kernel<<<1, 32>>>(out);
}

// round 12
// speedup vs baseline: 5.2018x; 1.0376x over previous
#include <cuda_runtime.h>
#include <cuda_fp16.h>
#include <math.h>
#include <stdint.h>

#define NE 8
#define DM 1024
#define NBz 4
#define NSz 2048
#define NT 8192           // tokens
#define NP 16384          // (token,slot) pairs

// ---------------- device scratch (no allocation allowed) -------------------
__device__ __align__(1024) __half g_xh[(size_t)NT * DM];
__device__ __align__(1024) __half g_w1h[(size_t)NE * DM * DM];   // natural [e][k][n]
__device__ __align__(1024) __half g_w2h[(size_t)NE * DM * DM];
__device__ __align__(1024) __half g_hh[(size_t)NP * DM];
__device__ int   g_order[NP];
__device__ float g_wt[NP];
__device__ int   g_eid[NP];
__device__ int   g_count[NE], g_off[NE], g_pos[NE];
__device__ int   g_toff[NE + 1];
__device__ float g_zsum, g_proxy[NBz * NE], g_dens[NBz * NE];

// ---------------- helpers ---------------------------------------------------
__device__ __forceinline__ uint32_t smem_u32(const void* p) {
    uint32_t a;
    asm("{ .reg .u64 t; cvta.to.shared.u64 t, %1; cvt.u32.u64 %0, t; }" : "=r"(a) : "l"(p));
    return a;
}
__device__ __forceinline__ void cp16(uint32_t dst, const void* src) {
    asm volatile("cp.async.cg.shared.global [%0], [%1], 16;" :: "r"(dst), "l"(src));
}
__device__ __forceinline__ void cp_commit() { asm volatile("cp.async.commit_group;" ::: "memory"); }
__device__ __forceinline__ void cp_wait1() { asm volatile("cp.async.wait_group 1;" ::: "memory"); }
__device__ __forceinline__ void cp_wait0() { asm volatile("cp.async.wait_group 0;" ::: "memory"); }

__device__ __forceinline__ void ldmat4(uint32_t* r, uint32_t addr) {
    asm volatile("ldmatrix.sync.aligned.m8n8.x4.shared.b16 {%0,%1,%2,%3}, [%4];"
                 : "=r"(r[0]), "=r"(r[1]), "=r"(r[2]), "=r"(r[3]) : "r"(addr));
}
__device__ __forceinline__ void ldmat2t(uint32_t* r, uint32_t addr) {
    asm volatile("ldmatrix.sync.aligned.m8n8.x2.trans.shared.b16 {%0,%1}, [%2];"
                 : "=r"(r[0]), "=r"(r[1]) : "r"(addr));
}
__device__ __forceinline__ void mma_f16(float* c, const uint32_t* a, const uint32_t* b) {
    asm volatile("mma.sync.aligned.m16n8k16.row.col.f32.f16.f16.f32 "
                 "{%0,%1,%2,%3}, {%4,%5,%6,%7}, {%8,%9}, {%0,%1,%2,%3};"
                 : "+f"(c[0]), "+f"(c[1]), "+f"(c[2]), "+f"(c[3])
                 : "r"(a[0]), "r"(a[1]), "r"(a[2]), "r"(a[3]), "r"(b[0]), "r"(b[1]));
}
__device__ __forceinline__ float gelu_exact(float v) {
    return 0.5f * v * (1.0f + erff(v * 0.70710678118654752f));
}
__device__ __forceinline__ void cvt4(const float* src, __half2* dst, size_t i) {
    float4 v = ((const float4*)src)[i];
    dst[2 * i]     = __half2(__float2half_rn(v.x), __float2half_rn(v.y));
    dst[2 * i + 1] = __half2(__float2half_rn(v.z), __float2half_rn(v.w));
}

// ---------------- init / gating / scatter ----------------------------------
__global__ void init_kernel() {
    int t = threadIdx.x;
    if (t < NE) { g_count[t] = 0; g_pos[t] = 0; }
    if (t == 0) g_zsum = 0.0f;
    if (t < NBz * NE) { g_proxy[t] = 0.0f; g_dens[t] = 0.0f; }
}

// gating + fp16(x) + fp16(W1) conversion + zero(out)
__global__ __launch_bounds__(256) void gate_kernel(
    const float* __restrict__ x, const float* __restrict__ Wg,
    const float* __restrict__ W1, float* __restrict__ out) {
    __shared__ float xs[DM];
    __shared__ float logits[NE];
    int t = blockIdx.x;
    const float* xr = x + (size_t)t * DM;
    for (int i = threadIdx.x; i < DM; i += blockDim.x) xs[i] = xr[i];
    __syncthreads();
    for (int i = threadIdx.x; i < DM / 2; i += blockDim.x) {
        __half2 v = __half2(__float2half_rn(xs[2 * i]), __float2half_rn(xs[2 * i + 1]));
        ((__half2*)(g_xh + (size_t)t * DM))[i] = v;
    }
    int w = threadIdx.x >> 5, lane = threadIdx.x & 31;
    const float* wg = Wg + w * DM;
    float s = 0.0f;
    for (int k = lane; k < DM; k += 32) s += xs[k] * wg[k];
#pragma unroll
    for (int o = 16; o; o >>= 1) s += __shfl_xor_sync(0xffffffffu, s, o);
    if (lane == 0) logits[w] = s;
    __syncthreads();
    if (threadIdx.x == 0) {
        float m = -1e30f;
#pragma unroll
        for (int e = 0; e < NE; e++) m = fmaxf(m, logits[e]);
        float p[NE], sum = 0.0f;
#pragma unroll
        for (int e = 0; e < NE; e++) { p[e] = expf(logits[e] - m); sum += p[e]; }
        float inv_sum = 1.0f / sum;
        float z = m + logf(sum);
        atomicAdd(&g_zsum, z * z);
        int b = t / NSz;
#pragma unroll
        for (int e = 0; e < NE; e++) atomicAdd(&g_proxy[b * NE + e], p[e] * inv_sum);
        int i0 = 0;
#pragma unroll
        for (int e = 1; e < NE; e++) if (p[e] > p[i0]) i0 = e;
        int i1 = (i0 == 0) ? 1 : 0;
#pragma unroll
        for (int e = 0; e < NE; e++) if (e != i0 && p[e] > p[i1]) i1 = e;
        atomicAdd(&g_dens[b * NE + i0], 1.0f);
        float v0 = p[i0], v1 = p[i1];
        float invw = 1.0f / (v0 + v1);
        g_wt[2 * t] = v0 * invw;
        g_wt[2 * t + 1] = v1 * invw;
        g_eid[2 * t] = i0;
        g_eid[2 * t + 1] = i1;
        atomicAdd(&g_count[i0], 1);
        atomicAdd(&g_count[i1], 1);
    }
    // extra grid-wide work: one float4 of W1 and one float4 of out per thread
    size_t gi = (size_t)blockIdx.x * blockDim.x + threadIdx.x;
    cvt4(W1, (__half2*)g_w1h, gi);                      // NE*DM*DM/4 == NT*256 exactly
    ((float4*)out)[gi] = make_float4(0.f, 0.f, 0.f, 0.f);   // NT*DM/4 == NT*256 exactly
}

__global__ void scan_kernel() {
    if (threadIdx.x == 0) {
        int acc = 0, tacc = 0;
#pragma unroll
        for (int e = 0; e < NE; e++) {
            g_off[e] = acc;
            g_toff[e] = tacc;
            acc += g_count[e];
            tacc += ((g_count[e] + 127) >> 7) * 8;   // rowtiles * n-tiles
        }
        g_toff[NE] = tacc;
    }
}

__global__ void scatter_kernel() {
    int p = blockIdx.x * blockDim.x + threadIdx.x;
    if (p >= NP) return;
    int e = g_eid[p];
    int idx = atomicAdd(&g_pos[e], 1);
    g_order[g_off[e] + idx] = p;
}

// ---------------- HMMA GEMM (single fp16 product, persistent tiles) --------
// CTA tile 128x128, K chunk 64, 8 warps (2x4), warp tile 64x32, 3-stage cp.async
#define BM 128
#define BN 128
#define BK 64
#define NCHUNK (DM / BK)                 // 16
#define ASTRIDE 144                      // 128B data + 16B pad
#define BSTRIDE 272                      // 256B data + 16B pad
#define A_BYTES (BM * ASTRIDE)           // 18432
#define B_BYTES (BK * BSTRIDE)           // 17408
#define STAGE_BYTES (A_BYTES + B_BYTES)  // 35840
#define A_OFF(s) ((s) * STAGE_BYTES)
#define B_OFF(s) ((s) * STAGE_BYTES + A_BYTES)
#define TOKS_OFF (3 * STAGE_BYTES)       // 107520
#define PV_OFF   (TOKS_OFF + 512)
#define WV_OFF   (PV_OFF + 512)
#define SMEM_TOTAL (WV_OFF + 512)        // 109056
#define NGEMM_CTAS 296

template <int PHASE>
__global__ __launch_bounds__(256, 2) void moe_gemm(
    const float* __restrict__ bias,
    const float* __restrict__ W2src,    // phase 1 only: convert W2 in tail
    float* __restrict__ outp) {         // phase 2 only: atomic output
    extern __shared__ char smem[];
    uint32_t sb = smem_u32(smem);
    int tid = threadIdx.x;
    int wid = tid >> 5, lane = tid & 31;
    int wr = wid >> 2, wc = wid & 3;      // 2 x 4 warp grid
    int m0w = wr * 64, n0w = wc * 32;

    int* toks = (int*)(smem + TOKS_OFF);
    int ntiles = g_toff[NE];

    for (int t = blockIdx.x; t < ntiles; t += NGEMM_CTAS) {
        // decode tile -> (expert, row tile, n tile)
        int e = 0;
#pragma unroll
        for (int k = 1; k < NE; k++) if (t >= g_toff[k]) e = k;
        int tl = t - g_toff[e];
        int row0 = (tl >> 3) * BM;
        int n0 = (tl & 7) * BN;
        int cnt = g_count[e];
        int base = g_off[e];

        __syncthreads();   // previous tile's epilogue smem reads done
        if (tid < BM) {
            int r = row0 + tid;
            if (PHASE == 1) {
                toks[tid] = (r < cnt) ? (g_order[base + r] >> 1) : 0;
            } else {
                toks[tid] = (r < cnt) ? (base + r) : 0;
                int p = (r < cnt) ? g_order[base + r] : 0;
                ((int*)(smem + PV_OFF))[tid] = p;
                ((float*)(smem + WV_OFF))[tid] = g_wt[p];
            }
        }
        __syncthreads();

        const __half* Ah = (PHASE == 1) ? g_xh : g_hh;
        const __half* Wh = ((PHASE == 1) ? g_w1h : g_w2h) + (size_t)e * DM * DM;

        float acc[4][4][4];
#pragma unroll
        for (int i = 0; i < 4; i++)
#pragma unroll
            for (int j = 0; j < 4; j++)
#pragma unroll
                for (int q = 0; q < 4; q++) acc[i][j][q] = 0.0f;

        auto load_chunk = [&](int c, int s) {
            int k0 = c * BK;
#pragma unroll
            for (int it = 0; it < 4; it++) {
                int i = tid + it * 256;
                int r = i >> 3, cq = i & 7;
                cp16(sb + A_OFF(s) + r * ASTRIDE + cq * 16,
                     Ah + (size_t)toks[r] * DM + k0 + cq * 8);
            }
#pragma unroll
            for (int it = 0; it < 4; it++) {
                int i = tid + it * 256;
                int k = i >> 4, cq = i & 15;
                cp16(sb + B_OFF(s) + k * BSTRIDE + cq * 16,
                     Wh + (size_t)(k0 + k) * DM + n0 + cq * 8);
            }
            cp_commit();
        };

        auto compute = [&](int s) {
#pragma unroll
            for (int kk = 0; kk < 4; kk++) {
                int kb = kk * 16;
                uint32_t a[4][4], b[4][2];
                int arow = m0w + (lane & 15);
                int acolb = (kb + ((lane & 16) ? 8 : 0)) * 2;
#pragma unroll
                for (int i = 0; i < 4; i++)
                    ldmat4(a[i], sb + A_OFF(s) + (arow + i * 16) * ASTRIDE + acolb);
                int brow = kb + (lane & 15);
#pragma unroll
                for (int j = 0; j < 4; j++)
                    ldmat2t(b[j], sb + B_OFF(s) + brow * BSTRIDE + (n0w + j * 8) * 2);
#pragma unroll
                for (int i = 0; i < 4; i++)
#pragma unroll
                    for (int j = 0; j < 4; j++) mma_f16(acc[i][j], a[i], b[j]);
            }
        };

        load_chunk(0, 0);
        load_chunk(1, 1);
        for (int c = 0; c < NCHUNK; c++) {
            int s = c % 3;
            if (c < NCHUNK - 1) cp_wait1(); else cp_wait0();
            __syncthreads();
            if (c + 2 < NCHUNK) load_chunk(c + 2, (c + 2) % 3);
            compute(s);
        }

        // ---------------- epilogue ----------------
#pragma unroll
        for (int i = 0; i < 4; i++) {
            int rb = m0w + i * 16 + (lane >> 2);
#pragma unroll
            for (int j = 0; j < 4; j++) {
                int gcol = n0 + n0w + j * 8 + (lane & 3) * 2;
                float bv0 = bias[e * DM + gcol];
                float bv1 = bias[e * DM + gcol + 1];
#pragma unroll
                for (int h = 0; h < 2; h++) {
                    int r = rb + h * 8;
                    if (row0 + r >= cnt) continue;
                    float v0 = acc[i][j][2 * h]     + bv0;
                    float v1 = acc[i][j][2 * h + 1] + bv1;
                    if (PHASE == 1) {
                        float gg0 = gelu_exact(v0), gg1 = gelu_exact(v1);
                        __half2 hv = __half2(__float2half_rn(gg0), __float2half_rn(gg1));
                        size_t o = (size_t)(base + row0 + r) * DM + gcol;
                        *(__half2*)(g_hh + o) = hv;
                    } else {
                        float wv = ((float*)(smem + WV_OFF))[r];
                        int p = ((int*)(smem + PV_OFF))[r];
                        size_t o = (size_t)(p >> 1) * DM + gcol;
                        atomicAdd(&outp[o],     v0 * wv);
                        atomicAdd(&outp[o + 1], v1 * wv);
                    }
                }
            }
        }
    }

    // ---------------- phase-1 tail: convert W2 (overlaps straggler tiles) --
    if (PHASE == 1) {
        const size_t total = (size_t)NE * DM * DM / 4;   // float4 count
        for (size_t i = (size_t)blockIdx.x * 256 + tid; i < total;
             i += (size_t)NGEMM_CTAS * 256)
            cvt4(W2src, (__half2*)g_w2h, i);
    }
}

// ---------------- losses -----------------------------------------------------
__global__ void finalize_kernel(float* __restrict__ out) {
    if (threadIdx.x == 0) {
        float zloss = g_zsum / (float)NT;
        float bal = 0.0f;
#pragma unroll
        for (int i = 0; i < NBz * NE; i++)
            bal += (g_proxy[i] / (float)NSz) * (g_dens[i] / (float)NSz);
        bal = bal / (float)(NBz * NE) * (float)(NE * NE);
        out[(size_t)NT * DM]     = bal * 0.01f + zloss * 0.001f;
        out[(size_t)NT * DM + 1] = bal;
    }
}

// ---------------- launch ----------------------------------------------------
extern "C" void kernel_launch(void* const* d_in, const int* in_sizes, int n_in,
                              void* d_out, int out_size) {
    const float* x  = (const float*)d_in[0];
    const float* Wg = (const float*)d_in[1];
    const float* W1 = (const float*)d_in[2];
    const float* b1 = (const float*)d_in[3];
    const float* W2 = (const float*)d_in[4];
    const float* b2 = (const float*)d_in[5];
    float* out = (float*)d_out;

    cudaFuncSetAttribute(moe_gemm<1>, cudaFuncAttributeMaxDynamicSharedMemorySize, SMEM_TOTAL);
    cudaFuncSetAttribute(moe_gemm<2>, cudaFuncAttributeMaxDynamicSharedMemorySize, SMEM_TOTAL);

    init_kernel<<<1, 32>>>();
    gate_kernel<<<NT, 256>>>(x, Wg, W1, out);
    scan_kernel<<<1, 32>>>();
    scatter_kernel<<<NP / 256, 256>>>();

    moe_gemm<1><<<NGEMM_CTAS, 256, SMEM_TOTAL>>>(b1, W2, nullptr);
    moe_gemm<2><<<NGEMM_CTAS, 256, SMEM_TOTAL>>>(b2, nullptr, out);
    finalize_kernel<<<1, 32>>>(out);
}